// round 13
// baseline (speedup 1.0000x reference)
#include <cuda_runtime.h>
#include <cuda_bf16.h>
#include <cstdint>
#include <cstddef>

// Problem constants
#define Bz 4
#define Tz 2048
#define Cz 1024
#define Hz 16
#define HSz 64
#define Mz (Bz*Tz)          // 8192
#define N3 (3*Cz)           // 3072
#define Kz 1024

// ---------------------------------------------------------------------------
// Scratch (__device__ globals; allocation-free rule)
// ---------------------------------------------------------------------------
__device__ __nv_bfloat16 g_xh[(size_t)Mz * Cz];
__device__ __nv_bfloat16 g_xl[(size_t)Mz * Cz];
__device__ __nv_bfloat16 g_bTh[(size_t)N3 * Cz];   // W^T (3072 x 1024)
__device__ __nv_bfloat16 g_bTl[(size_t)N3 * Cz];
__device__ __nv_bfloat16 g_pTh[(size_t)Cz * Cz];   // proj_w^T
__device__ __nv_bfloat16 g_pTl[(size_t)Cz * Cz];
__device__ __nv_bfloat16 g_qkvh[(size_t)Mz * N3];  // qkv hi (B*T, 3C)
__device__ __nv_bfloat16 g_qkvl[(size_t)Mz * N3];  // qkv lo
__device__ __nv_bfloat16 g_ah[(size_t)Mz * Cz];    // attn hi
__device__ __nv_bfloat16 g_al[(size_t)Mz * Cz];    // attn lo

// ---------------------------------------------------------------------------
// Helpers
// ---------------------------------------------------------------------------
__device__ __forceinline__ uint32_t smem_u32(const void* p) {
    uint32_t a;
    asm("{ .reg .u64 t; cvta.to.shared.u64 t, %1; cvt.u32.u64 %0, t; }" : "=r"(a) : "l"(p));
    return a;
}

__device__ __forceinline__ void cpasync16(uint32_t dst, const void* src) {
    asm volatile("cp.async.cg.shared.global [%0], [%1], 16;" :: "r"(dst), "l"(src));
}
__device__ __forceinline__ void cp_commit() {
    asm volatile("cp.async.commit_group;" ::: "memory");
}
__device__ __forceinline__ void cp_wait1() {
    asm volatile("cp.async.wait_group 1;" ::: "memory");
}
__device__ __forceinline__ void cp_wait0() {
    asm volatile("cp.async.wait_group 0;" ::: "memory");
}

__device__ __forceinline__ void ldmx4(uint32_t* r, uint32_t addr) {
    asm volatile("ldmatrix.sync.aligned.m8n8.x4.shared.b16 {%0,%1,%2,%3}, [%4];"
                 : "=r"(r[0]), "=r"(r[1]), "=r"(r[2]), "=r"(r[3]) : "r"(addr));
}

__device__ __forceinline__ void ldmx4t(uint32_t* r, uint32_t addr) {
    asm volatile("ldmatrix.sync.aligned.m8n8.x4.trans.shared.b16 {%0,%1,%2,%3}, [%4];"
                 : "=r"(r[0]), "=r"(r[1]), "=r"(r[2]), "=r"(r[3]) : "r"(addr));
}

__device__ __forceinline__ void mma16816(float* d, const uint32_t* a, const uint32_t* b) {
    asm volatile("mma.sync.aligned.m16n8k16.row.col.f32.bf16.bf16.f32 "
                 "{%0,%1,%2,%3}, {%4,%5,%6,%7}, {%8,%9}, {%0,%1,%2,%3};"
                 : "+f"(d[0]), "+f"(d[1]), "+f"(d[2]), "+f"(d[3])
                 : "r"(a[0]), "r"(a[1]), "r"(a[2]), "r"(a[3]), "r"(b[0]), "r"(b[1]));
}

// split two floats into packed bf16 hi and lo (low element first)
__device__ __forceinline__ void split2(float a, float b, uint32_t& hi, uint32_t& lo) {
    __nv_bfloat16 ha = __float2bfloat16_rn(a), hb = __float2bfloat16_rn(b);
    __nv_bfloat16 la = __float2bfloat16_rn(a - __bfloat162float(ha));
    __nv_bfloat16 lb = __float2bfloat16_rn(b - __bfloat162float(hb));
    __nv_bfloat162 H(ha, hb), L(la, lb);
    hi = *reinterpret_cast<uint32_t*>(&H);
    lo = *reinterpret_cast<uint32_t*>(&L);
}

// ---------------------------------------------------------------------------
// Split fp32 -> (hi, lo) bf16 (coalesced both sides)
// ---------------------------------------------------------------------------
__global__ void split_kernel(const float* __restrict__ in,
                             __nv_bfloat16* __restrict__ hi,
                             __nv_bfloat16* __restrict__ lo, int n4) {
    int i = blockIdx.x * blockDim.x + threadIdx.x;
    if (i >= n4) return;
    float4 v = ((const float4*)in)[i];
    float f[4] = {v.x, v.y, v.z, v.w};
    __nv_bfloat16 h[4], l[4];
#pragma unroll
    for (int j = 0; j < 4; j++) {
        h[j] = __float2bfloat16(f[j]);
        l[j] = __float2bfloat16(f[j] - __bfloat162float(h[j]));
    }
    ((__nv_bfloat162*)hi)[2 * i]     = __nv_bfloat162(h[0], h[1]);
    ((__nv_bfloat162*)hi)[2 * i + 1] = __nv_bfloat162(h[2], h[3]);
    ((__nv_bfloat162*)lo)[2 * i]     = __nv_bfloat162(l[0], l[1]);
    ((__nv_bfloat162*)lo)[2 * i + 1] = __nv_bfloat162(l[2], l[3]);
}

// ---------------------------------------------------------------------------
// Tiled-transpose pack of Wq/Wk/Wv (H,C,HS) -> B^T (3072 x 1024) hi/lo.
// grid: (HSz/32, Cz/32, 3*Hz), block (32,8)
// ---------------------------------------------------------------------------
__global__ void packw_t_kernel(const float* __restrict__ Wq, const float* __restrict__ Wk,
                               const float* __restrict__ Wv,
                               __nv_bfloat16* __restrict__ bh, __nv_bfloat16* __restrict__ bl) {
    __shared__ float tile[32][33];
    const int wh = blockIdx.z;
    const int w = wh >> 4;
    const int h = wh & 15;
    const float* W = (w == 0) ? Wq : ((w == 1) ? Wk : Wv);
    const int d0 = blockIdx.x * 32;
    const int c0 = blockIdx.y * 32;
    const int tx = threadIdx.x;
    const int ty = threadIdx.y;

#pragma unroll
    for (int i = 0; i < 32; i += 8) {
        int c = c0 + ty + i;
        tile[ty + i][tx] = W[((size_t)h * Cz + c) * HSz + d0 + tx];
    }
    __syncthreads();
#pragma unroll
    for (int i = 0; i < 32; i += 8) {
        int d = d0 + ty + i;
        float v = tile[tx][ty + i];
        __nv_bfloat16 hi = __float2bfloat16(v);
        size_t n = (size_t)w * 1024 + h * 64 + d;
        bh[n * Cz + c0 + tx] = hi;
        bl[n * Cz + c0 + tx] = __float2bfloat16(v - __bfloat162float(hi));
    }
}

// proj_w (K,N) -> proj_w^T (N,K) hi/lo, tiled transpose. grid (32,32), block (32,8)
__global__ void packp_t_kernel(const float* __restrict__ pw,
                               __nv_bfloat16* __restrict__ ph, __nv_bfloat16* __restrict__ pl) {
    __shared__ float tile[32][33];
    const int n0 = blockIdx.x * 32;
    const int k0 = blockIdx.y * 32;
    const int tx = threadIdx.x;
    const int ty = threadIdx.y;
#pragma unroll
    for (int i = 0; i < 32; i += 8) {
        int k = k0 + ty + i;
        tile[ty + i][tx] = pw[(size_t)k * Cz + n0 + tx];
    }
    __syncthreads();
#pragma unroll
    for (int i = 0; i < 32; i += 8) {
        int n = n0 + ty + i;
        float v = tile[tx][ty + i];
        __nv_bfloat16 hi = __float2bfloat16(v);
        ph[(size_t)n * Cz + k0 + tx] = hi;
        pl[(size_t)n * Cz + k0 + tx] = __float2bfloat16(v - __bfloat162float(hi));
    }
}

// ---------------------------------------------------------------------------
// mma.sync split-bf16 GEMM, 256x128 CTA tile, warp tile 64x64, K-chunk 64,
// 2-stage cp.async (proven pipeline shape). 3-term: Ah*Bh + Al*Bh + Ah*Bl.
// smem/stage: Ah 32K | Al 32K | Bh 16K | Bl 16K = 96KB; 2 stages = 192KB.
// ---------------------------------------------------------------------------
#define AT_BYTES 32768            // 256x64 bf16 tile
#define BT_BYTES 16384            // 128x64 bf16 tile
#define GSTAGE (2 * AT_BYTES + 2 * BT_BYTES)   // 98304 per stage
#define NCHUNK (Kz / 64)          // 16

__global__ __launch_bounds__(256)
void mma_gemm_kernel(const __nv_bfloat16* __restrict__ Ah, const __nv_bfloat16* __restrict__ Al,
                     const __nv_bfloat16* __restrict__ Bh, const __nv_bfloat16* __restrict__ Bl,
                     float* __restrict__ Cf, const float* __restrict__ bias, int N,
                     __nv_bfloat16* __restrict__ Ch, __nv_bfloat16* __restrict__ Cl) {
    extern __shared__ char dyn_smem[];
    const uint32_t sb = smem_u32(dyn_smem);

    const int tid  = threadIdx.x;
    const int wid  = tid >> 5;
    const int lane = tid & 31;
    const int wm = wid >> 1;          // 0..3 (64 rows each)
    const int wn = wid & 1;           // 0..1 (64 cols each)
    const size_t bn = (size_t)blockIdx.x * 128;
    const size_t bm = (size_t)blockIdx.y * 256;

    const int lr = lane & 7;
    const uint32_t sw = (uint32_t)lr << 4;
    const uint32_t aRow = (uint32_t)(wm * 64 + lr + ((lane >> 3) & 1) * 8) * 128;
    const uint32_t aCsel = ((lane >> 4) & 1) * 16;
    const uint32_t bRow = (uint32_t)(wn * 64 + lr + ((lane >> 4) & 1) * 8) * 128;
    const uint32_t bCsel = ((lane >> 3) & 1) * 16;

    float acc[4][8][4];
#pragma unroll
    for (int i = 0; i < 4; i++)
#pragma unroll
        for (int j = 0; j < 8; j++)
#pragma unroll
            for (int q = 0; q < 4; q++) acc[i][j][q] = 0.f;

    const __nv_bfloat16* asrc[2] = {Ah + bm * Kz, Al + bm * Kz};
    const __nv_bfloat16* bsrc[2] = {Bh + bn * Kz, Bl + bn * Kz};

    // per-thread load geometry: A tiles 8 x 16B, B tiles 4 x 16B
    size_t goffA[8];
    uint32_t soffA[8];
#pragma unroll
    for (int i = 0; i < 8; i++) {
        int slot = tid + i * 256;             // 0..2047
        int r = slot >> 3;                    // 0..255
        int g = slot & 7;
        goffA[i] = (size_t)r * Kz + g * 8;
        soffA[i] = (uint32_t)(r * 128) + (((uint32_t)g * 16) ^ (((uint32_t)r & 7) * 16));
    }
    size_t goffB[4];
    uint32_t soffB[4];
#pragma unroll
    for (int i = 0; i < 4; i++) {
        int slot = tid + i * 256;             // 0..1023
        int r = slot >> 3;                    // 0..127
        int g = slot & 7;
        goffB[i] = (size_t)r * Kz + g * 8;
        soffB[i] = (uint32_t)(r * 128) + (((uint32_t)g * 16) ^ (((uint32_t)r & 7) * 16));
    }

#define GEMM_ISSUE(kc, stbase)                                                  \
    do {                                                                        \
        _Pragma("unroll")                                                       \
        for (int j = 0; j < 2; j++) {                                           \
            const __nv_bfloat16* s_ = asrc[j] + (kc) * 64;                      \
            _Pragma("unroll")                                                   \
            for (int i = 0; i < 8; i++)                                         \
                cpasync16((stbase) + j * AT_BYTES + soffA[i], s_ + goffA[i]);   \
        }                                                                       \
        _Pragma("unroll")                                                       \
        for (int j = 0; j < 2; j++) {                                           \
            const __nv_bfloat16* s_ = bsrc[j] + (kc) * 64;                      \
            _Pragma("unroll")                                                   \
            for (int i = 0; i < 4; i++)                                         \
                cpasync16((stbase) + 2 * AT_BYTES + j * BT_BYTES + soffB[i], s_ + goffB[i]); \
        }                                                                       \
        cp_commit();                                                            \
    } while (0)

    GEMM_ISSUE(0, sb);
    GEMM_ISSUE(1, sb + GSTAGE);

    for (int kc = 0; kc < NCHUNK; kc++) {
        if (kc < NCHUNK - 1) cp_wait1(); else cp_wait0();
        __syncthreads();

        const uint32_t st = sb + (uint32_t)(kc & 1) * GSTAGE;
        const uint32_t sAh = st, sAl = st + AT_BYTES;
        const uint32_t sBh = st + 2 * AT_BYTES, sBl = st + 2 * AT_BYTES + BT_BYTES;

#pragma unroll
        for (int ks = 0; ks < 4; ks++) {
            const uint32_t acol = sw ^ ((uint32_t)ks * 32 + aCsel);
            const uint32_t bcol = sw ^ ((uint32_t)ks * 32 + bCsel);
            uint32_t ah[4][4], al[4][4], bb[8][2];
#pragma unroll
            for (int mt = 0; mt < 4; mt++)
                ldmx4(ah[mt], sAh + aRow + mt * 2048 + acol);
#pragma unroll
            for (int mt = 0; mt < 4; mt++)
                ldmx4(al[mt], sAl + aRow + mt * 2048 + acol);
#pragma unroll
            for (int np = 0; np < 4; np++) {
                uint32_t q[4];
                ldmx4(q, sBh + bRow + np * 2048 + bcol);
                bb[np * 2][0] = q[0]; bb[np * 2][1] = q[1];
                bb[np * 2 + 1][0] = q[2]; bb[np * 2 + 1][1] = q[3];
            }
#pragma unroll
            for (int mt = 0; mt < 4; mt++)
#pragma unroll
                for (int nt = 0; nt < 8; nt++) {
                    mma16816(acc[mt][nt], ah[mt], bb[nt]);
                    mma16816(acc[mt][nt], al[mt], bb[nt]);
                }
#pragma unroll
            for (int np = 0; np < 4; np++) {
                uint32_t q[4];
                ldmx4(q, sBl + bRow + np * 2048 + bcol);
                bb[np * 2][0] = q[0]; bb[np * 2][1] = q[1];
                bb[np * 2 + 1][0] = q[2]; bb[np * 2 + 1][1] = q[3];
            }
#pragma unroll
            for (int mt = 0; mt < 4; mt++)
#pragma unroll
                for (int nt = 0; nt < 8; nt++)
                    mma16816(acc[mt][nt], ah[mt], bb[nt]);   // Ah*Bl cross term
        }
        __syncthreads();
        if (kc + 2 < NCHUNK) GEMM_ISSUE(kc + 2, st);
    }

    // Epilogue
    if (Cf) {
#pragma unroll
        for (int mt = 0; mt < 4; mt++) {
            size_t r0 = bm + wm * 64 + mt * 16 + (lane >> 2);
#pragma unroll
            for (int nt = 0; nt < 8; nt++) {
                size_t c0 = bn + wn * 64 + nt * 8 + (lane & 3) * 2;
                float b0 = 0.f, b1 = 0.f;
                if (bias) { b0 = bias[c0]; b1 = bias[c0 + 1]; }
                float2 v0 = {acc[mt][nt][0] + b0, acc[mt][nt][1] + b1};
                float2 v1 = {acc[mt][nt][2] + b0, acc[mt][nt][3] + b1};
                *(float2*)(Cf + r0 * (size_t)N + c0)       = v0;
                *(float2*)(Cf + (r0 + 8) * (size_t)N + c0) = v1;
            }
        }
    } else {
#pragma unroll
        for (int mt = 0; mt < 4; mt++) {
            size_t r0 = bm + wm * 64 + mt * 16 + (lane >> 2);
#pragma unroll
            for (int nt = 0; nt < 8; nt++) {
                size_t c0 = bn + wn * 64 + nt * 8 + (lane & 3) * 2;
                uint32_t h0, l0, h1, l1;
                split2(acc[mt][nt][0], acc[mt][nt][1], h0, l0);
                split2(acc[mt][nt][2], acc[mt][nt][3], h1, l1);
                *(uint32_t*)(Ch + r0 * (size_t)N + c0)       = h0;
                *(uint32_t*)(Cl + r0 * (size_t)N + c0)       = l0;
                *(uint32_t*)(Ch + (r0 + 8) * (size_t)N + c0) = h1;
                *(uint32_t*)(Cl + (r0 + 8) * (size_t)N + c0) = l1;
            }
        }
    }
}

// ---------------------------------------------------------------------------
// mma.sync causal flash attention, 2-stage cp.async K/V pipeline.
// (proven round-10/12 structure, unchanged)
// ---------------------------------------------------------------------------
#define FKT 8192                 // one 64x64 bf16 tile
#define FSTAGE (4 * FKT)         // 32768 per stage (Kh,Kl,Vh,Vl)

__global__ __launch_bounds__(256)
void flash_mma_kernel(const __nv_bfloat16* __restrict__ qh_, const __nv_bfloat16* __restrict__ ql_,
                      __nv_bfloat16* __restrict__ oh_, __nv_bfloat16* __restrict__ ol_) {
    extern __shared__ char dyn_smem[];
    const uint32_t sb = smem_u32(dyn_smem);
    const uint32_t sQh = sb, sQl = sb + 16384;      // Q staging (before pipeline starts)

    const int tid = threadIdx.x;
    const int wid = tid >> 5;
    const int lane = tid & 31;
    const int lr = lane & 7;
    const uint32_t sw = (uint32_t)lr << 4;
    const int qt = gridDim.x - 1 - blockIdx.x;     // heavy tiles first
    const int t0 = qt * 128;
    const int b  = blockIdx.y >> 4;
    const int h  = blockIdx.y & 15;

    const size_t rowoff = (size_t)(b * Tz) * N3 + h * HSz;
    const __nv_bfloat16* Qsh = qh_ + rowoff;
    const __nv_bfloat16* Qsl = ql_ + rowoff;
    const __nv_bfloat16* kvsrc[4] = {Qsh + Cz, Qsl + Cz, Qsh + 2 * Cz, Qsl + 2 * Cz};

    // ---- Stage Q (128 rows x 64 bf16, hi+lo), swizzled ----
    {
        const __nv_bfloat16* qsrc[2] = {Qsh, Qsl};
        const uint32_t qdst[2] = {sQh, sQl};
#pragma unroll
        for (int j = 0; j < 2; j++)
#pragma unroll
            for (int i = 0; i < 4; i++) {
                int slot = tid + i * 256;
                int r = slot >> 3;
                int g = slot & 7;
                uint4 v = *(const uint4*)(qsrc[j] + (size_t)(t0 + r) * N3 + g * 8);
                uint32_t off = (uint32_t)(r * 128) + (((uint32_t)g * 16) ^ (((uint32_t)r & 7) * 16));
                asm volatile("st.shared.v4.b32 [%0], {%1,%2,%3,%4};"
                             :: "r"(qdst[j] + off), "r"(v.x), "r"(v.y), "r"(v.z), "r"(v.w));
            }
    }
    __syncthreads();

    // ---- Extract Q fragments ----
    uint32_t qfh[4][4], qfl[4][4];
    {
        const uint32_t aoff = (uint32_t)(wid * 16 + lr + ((lane >> 3) & 1) * 8) * 128;
        const uint32_t acs = ((lane >> 4) & 1) * 16;
#pragma unroll
        for (int ks = 0; ks < 4; ks++) {
            ldmx4(qfh[ks], sQh + aoff + (((uint32_t)ks * 32 + acs) ^ sw));
            ldmx4(qfl[ks], sQl + aoff + (((uint32_t)ks * 32 + acs) ^ sw));
        }
    }
    __syncthreads();   // Q region now reusable for K/V pipeline

    float o[8][4];
#pragma unroll
    for (int i = 0; i < 8; i++)
#pragma unroll
        for (int j = 0; j < 4; j++) o[i][j] = 0.f;
    float m0 = -1e30f, m1 = -1e30f, l0 = 0.f, l1 = 0.f;

    const int gr0 = t0 + wid * 16 + (lane >> 2);
    const int gr1 = gr0 + 8;

    const uint32_t krow = (uint32_t)(((lane >> 4) & 1) * 8 + lr);
    const uint32_t kcs = ((lane >> 3) & 1) * 16;
    const uint32_t vrow = (uint32_t)(((lane >> 3) & 1) * 8 + lr);
    const uint32_t vcs = ((lane >> 4) & 1) * 16;

    // per-thread K/V load geometry: 2 x 16B per tile
    size_t fgoff[2];
    uint32_t fsoff[2];
#pragma unroll
    for (int i = 0; i < 2; i++) {
        int slot = tid + i * 256;
        int r = slot >> 3;
        int g = slot & 7;
        fgoff[i] = (size_t)r * N3 + g * 8;
        fsoff[i] = (uint32_t)(r * 128) + (((uint32_t)g * 16) ^ (((uint32_t)r & 7) * 16));
    }

#define FLASH_ISSUE(it, stbase)                                                 \
    do {                                                                        \
        const size_t kb_ = (size_t)(it) * 64 * N3;                              \
        _Pragma("unroll")                                                       \
        for (int j = 0; j < 4; j++) {                                           \
            _Pragma("unroll")                                                   \
            for (int i = 0; i < 2; i++)                                         \
                cpasync16((stbase) + j * FKT + fsoff[i], kvsrc[j] + kb_ + fgoff[i]); \
        }                                                                       \
        cp_commit();                                                            \
    } while (0)

    const int nkt = 2 * qt + 2;    // >= 2 always
    FLASH_ISSUE(0, sb);
    FLASH_ISSUE(1, sb + FSTAGE);

    for (int it = 0; it < nkt; it++) {
        const int kt0 = it * 64;
        if (it < nkt - 1) cp_wait1(); else cp_wait0();
        __syncthreads();

        const uint32_t st = sb + (uint32_t)(it & 1) * FSTAGE;
        const uint32_t sKh = st, sKl = st + FKT, sVh = st + 2 * FKT, sVl = st + 3 * FKT;

        const bool alive = (kt0 <= t0 + wid * 16 + 15);
        if (alive) {
            // ---- S = Q K^T : 16x64 per warp, 3-term split ----
            float s[8][4];
#pragma unroll
            for (int i = 0; i < 8; i++)
#pragma unroll
                for (int j = 0; j < 4; j++) s[i][j] = 0.f;

#pragma unroll
            for (int ks = 0; ks < 4; ks++) {
                uint32_t bb[8][2];
#pragma unroll
                for (int np = 0; np < 4; np++) {
                    uint32_t q[4];
                    ldmx4(q, sKh + (np * 16 + krow) * 128 + (((uint32_t)ks * 32 + kcs) ^ sw));
                    bb[np * 2][0] = q[0]; bb[np * 2][1] = q[1];
                    bb[np * 2 + 1][0] = q[2]; bb[np * 2 + 1][1] = q[3];
                }
#pragma unroll
                for (int nt = 0; nt < 8; nt++) mma16816(s[nt], qfh[ks], bb[nt]);
#pragma unroll
                for (int nt = 0; nt < 8; nt++) mma16816(s[nt], qfl[ks], bb[nt]);
#pragma unroll
                for (int np = 0; np < 4; np++) {
                    uint32_t q[4];
                    ldmx4(q, sKl + (np * 16 + krow) * 128 + (((uint32_t)ks * 32 + kcs) ^ sw));
                    bb[np * 2][0] = q[0]; bb[np * 2][1] = q[1];
                    bb[np * 2 + 1][0] = q[2]; bb[np * 2 + 1][1] = q[3];
                }
#pragma unroll
                for (int nt = 0; nt < 8; nt++) mma16816(s[nt], qfh[ks], bb[nt]);
            }

            // ---- causal mask ----
            if (kt0 + 63 > t0 + wid * 16) {
                const int cbase = kt0 + 2 * (lane & 3);
#pragma unroll
                for (int nt = 0; nt < 8; nt++) {
                    int col = cbase + nt * 8;
                    if (col     > gr0) s[nt][0] = -1e30f;
                    if (col + 1 > gr0) s[nt][1] = -1e30f;
                    if (col     > gr1) s[nt][2] = -1e30f;
                    if (col + 1 > gr1) s[nt][3] = -1e30f;
                }
            }

            // ---- online softmax (warp-local; quad shuffles) ----
            float mx0 = m0, mx1 = m1;
#pragma unroll
            for (int nt = 0; nt < 8; nt++) {
                mx0 = fmaxf(mx0, fmaxf(s[nt][0], s[nt][1]));
                mx1 = fmaxf(mx1, fmaxf(s[nt][2], s[nt][3]));
            }
            mx0 = fmaxf(mx0, __shfl_xor_sync(0xffffffffu, mx0, 1));
            mx0 = fmaxf(mx0, __shfl_xor_sync(0xffffffffu, mx0, 2));
            mx1 = fmaxf(mx1, __shfl_xor_sync(0xffffffffu, mx1, 1));
            mx1 = fmaxf(mx1, __shfl_xor_sync(0xffffffffu, mx1, 2));
            float corr0 = __expf(m0 - mx0);
            float corr1 = __expf(m1 - mx1);
            float sum0 = 0.f, sum1 = 0.f;
#pragma unroll
            for (int nt = 0; nt < 8; nt++) {
                s[nt][0] = __expf(s[nt][0] - mx0); sum0 += s[nt][0];
                s[nt][1] = __expf(s[nt][1] - mx0); sum0 += s[nt][1];
                s[nt][2] = __expf(s[nt][2] - mx1); sum1 += s[nt][2];
                s[nt][3] = __expf(s[nt][3] - mx1); sum1 += s[nt][3];
            }
            sum0 += __shfl_xor_sync(0xffffffffu, sum0, 1);
            sum0 += __shfl_xor_sync(0xffffffffu, sum0, 2);
            sum1 += __shfl_xor_sync(0xffffffffu, sum1, 1);
            sum1 += __shfl_xor_sync(0xffffffffu, sum1, 2);
            m0 = mx0; m1 = mx1;
            l0 = l0 * corr0 + sum0;
            l1 = l1 * corr1 + sum1;
#pragma unroll
            for (int nt = 0; nt < 8; nt++) {
                o[nt][0] *= corr0; o[nt][1] *= corr0;
                o[nt][2] *= corr1; o[nt][3] *= corr1;
            }

            // ---- O += P V ----
#pragma unroll
            for (int ks = 0; ks < 4; ks++) {
                uint32_t pah[4], pal[4];
                split2(s[2 * ks][0],     s[2 * ks][1],     pah[0], pal[0]);
                split2(s[2 * ks][2],     s[2 * ks][3],     pah[1], pal[1]);
                split2(s[2 * ks + 1][0], s[2 * ks + 1][1], pah[2], pal[2]);
                split2(s[2 * ks + 1][2], s[2 * ks + 1][3], pah[3], pal[3]);

                uint32_t bv[8][2];
#pragma unroll
                for (int np = 0; np < 4; np++) {
                    uint32_t q[4];
                    ldmx4t(q, sVh + (ks * 16 + vrow) * 128 + (((uint32_t)np * 32 + vcs) ^ sw));
                    bv[np * 2][0] = q[0]; bv[np * 2][1] = q[1];
                    bv[np * 2 + 1][0] = q[2]; bv[np * 2 + 1][1] = q[3];
                }
#pragma unroll
                for (int nt = 0; nt < 8; nt++) mma16816(o[nt], pah, bv[nt]);
#pragma unroll
                for (int nt = 0; nt < 8; nt++) mma16816(o[nt], pal, bv[nt]);
#pragma unroll
                for (int np = 0; np < 4; np++) {
                    uint32_t q[4];
                    ldmx4t(q, sVl + (ks * 16 + vrow) * 128 + (((uint32_t)np * 32 + vcs) ^ sw));
                    bv[np * 2][0] = q[0]; bv[np * 2][1] = q[1];
                    bv[np * 2 + 1][0] = q[2]; bv[np * 2 + 1][1] = q[3];
                }
#pragma unroll
                for (int nt = 0; nt < 8; nt++) mma16816(o[nt], pah, bv[nt]);
            }
        }
        __syncthreads();
        if (it + 2 < nkt) FLASH_ISSUE(it + 2, st);
    }

    // ---- epilogue: normalize, split to bf16 hi/lo, write (B*T, C) ----
    const float inv0 = 1.f / l0;
    const float inv1 = 1.f / l1;
    const size_t obase = (size_t)b * Tz;
#pragma unroll
    for (int nt = 0; nt < 8; nt++) {
        size_t col = (size_t)h * HSz + nt * 8 + 2 * (lane & 3);
        uint32_t h0, lo0, h1, lo1;
        split2(o[nt][0] * inv0, o[nt][1] * inv0, h0, lo0);
        split2(o[nt][2] * inv1, o[nt][3] * inv1, h1, lo1);
        *(uint32_t*)(oh_ + (obase + gr0) * Cz + col) = h0;
        *(uint32_t*)(ol_ + (obase + gr0) * Cz + col) = lo0;
        *(uint32_t*)(oh_ + (obase + gr1) * Cz + col) = h1;
        *(uint32_t*)(ol_ + (obase + gr1) * Cz + col) = lo1;
    }
}

// ---------------------------------------------------------------------------
// Launch
// ---------------------------------------------------------------------------
extern "C" void kernel_launch(void* const* d_in, const int* in_sizes, int n_in,
                              void* d_out, int out_size) {
    (void)in_sizes; (void)n_in; (void)out_size;
    const float* x  = (const float*)d_in[0];
    const float* Wk = (const float*)d_in[1];
    const float* Wq = (const float*)d_in[2];
    const float* Wv = (const float*)d_in[3];
    const float* pw = (const float*)d_in[4];
    const float* pb = (const float*)d_in[5];
    float* out = (float*)d_out;

    __nv_bfloat16 *xh, *xl, *bTh, *bTl, *pTh, *pTl, *qkvh, *qkvl, *ah, *al;
    cudaGetSymbolAddress((void**)&xh,   g_xh);
    cudaGetSymbolAddress((void**)&xl,   g_xl);
    cudaGetSymbolAddress((void**)&bTh,  g_bTh);
    cudaGetSymbolAddress((void**)&bTl,  g_bTl);
    cudaGetSymbolAddress((void**)&pTh,  g_pTh);
    cudaGetSymbolAddress((void**)&pTl,  g_pTl);
    cudaGetSymbolAddress((void**)&qkvh, g_qkvh);
    cudaGetSymbolAddress((void**)&qkvl, g_qkvl);
    cudaGetSymbolAddress((void**)&ah,   g_ah);
    cudaGetSymbolAddress((void**)&al,   g_al);

    const int gemm_smem = 2 * GSTAGE;      // 196608
    cudaFuncSetAttribute(mma_gemm_kernel, cudaFuncAttributeMaxDynamicSharedMemorySize, gemm_smem);
    const int flash_smem = 2 * FSTAGE;     // 65536
    cudaFuncSetAttribute(flash_mma_kernel, cudaFuncAttributeMaxDynamicSharedMemorySize, flash_smem);

    // 1. split x, pack+split weights (tiled transposes, coalesced both sides)
    split_kernel<<<(Mz * Cz / 4 + 255) / 256, 256>>>(x, xh, xl, Mz * Cz / 4);
    packw_t_kernel<<<dim3(HSz / 32, Cz / 32, 3 * Hz), dim3(32, 8)>>>(Wq, Wk, Wv, bTh, bTl);
    packp_t_kernel<<<dim3(Cz / 32, Cz / 32), dim3(32, 8)>>>(pw, pTh, pTl);

    // 2. QKV projection -> bf16 hi/lo qkv   (256-row M tiles)
    mma_gemm_kernel<<<dim3(N3 / 128, Mz / 256), 256, gemm_smem>>>(
        xh, xl, bTh, bTl, nullptr, nullptr, N3, qkvh, qkvl);

    // 3. mma flash attention -> bf16 hi/lo attn
    flash_mma_kernel<<<dim3(Tz / 128, Bz * Hz), 256, flash_smem>>>(qkvh, qkvl, ah, al);

    // 4. output projection + bias -> fp32 out
    mma_gemm_kernel<<<dim3(Cz / 128, Mz / 256), 256, gemm_smem>>>(
        ah, al, pTh, pTl, out, pb, Cz, nullptr, nullptr);
}

// round 14
// speedup vs baseline: 1.0288x; 1.0288x over previous
#include <cuda_runtime.h>
#include <cuda_bf16.h>
#include <cstdint>
#include <cstddef>

// Problem constants
#define Bz 4
#define Tz 2048
#define Cz 1024
#define Hz 16
#define HSz 64
#define Mz (Bz*Tz)          // 8192
#define N3 (3*Cz)           // 3072
#define Kz 1024

// ---------------------------------------------------------------------------
// Scratch (__device__ globals; allocation-free rule)
// ---------------------------------------------------------------------------
__device__ __nv_bfloat16 g_xh[(size_t)Mz * Cz];
__device__ __nv_bfloat16 g_xl[(size_t)Mz * Cz];
__device__ __nv_bfloat16 g_bTh[(size_t)N3 * Cz];   // W^T (3072 x 1024)
__device__ __nv_bfloat16 g_bTl[(size_t)N3 * Cz];
__device__ __nv_bfloat16 g_pTh[(size_t)Cz * Cz];   // proj_w^T
__device__ __nv_bfloat16 g_pTl[(size_t)Cz * Cz];
__device__ __nv_bfloat16 g_qkvh[(size_t)Mz * N3];  // qkv hi (B*T, 3C)
__device__ __nv_bfloat16 g_qkvl[(size_t)Mz * N3];  // qkv lo
__device__ __nv_bfloat16 g_ah[(size_t)Mz * Cz];    // attn hi
__device__ __nv_bfloat16 g_al[(size_t)Mz * Cz];    // attn lo

// ---------------------------------------------------------------------------
// Helpers
// ---------------------------------------------------------------------------
__device__ __forceinline__ uint32_t smem_u32(const void* p) {
    uint32_t a;
    asm("{ .reg .u64 t; cvta.to.shared.u64 t, %1; cvt.u32.u64 %0, t; }" : "=r"(a) : "l"(p));
    return a;
}

__device__ __forceinline__ void cpasync16(uint32_t dst, const void* src) {
    asm volatile("cp.async.cg.shared.global [%0], [%1], 16;" :: "r"(dst), "l"(src));
}
__device__ __forceinline__ void cp_commit() {
    asm volatile("cp.async.commit_group;" ::: "memory");
}
__device__ __forceinline__ void cp_wait1() {
    asm volatile("cp.async.wait_group 1;" ::: "memory");
}
__device__ __forceinline__ void cp_wait0() {
    asm volatile("cp.async.wait_group 0;" ::: "memory");
}

__device__ __forceinline__ void ldmx4(uint32_t* r, uint32_t addr) {
    asm volatile("ldmatrix.sync.aligned.m8n8.x4.shared.b16 {%0,%1,%2,%3}, [%4];"
                 : "=r"(r[0]), "=r"(r[1]), "=r"(r[2]), "=r"(r[3]) : "r"(addr));
}

__device__ __forceinline__ void ldmx4t(uint32_t* r, uint32_t addr) {
    asm volatile("ldmatrix.sync.aligned.m8n8.x4.trans.shared.b16 {%0,%1,%2,%3}, [%4];"
                 : "=r"(r[0]), "=r"(r[1]), "=r"(r[2]), "=r"(r[3]) : "r"(addr));
}

__device__ __forceinline__ void mma16816(float* d, const uint32_t* a, const uint32_t* b) {
    asm volatile("mma.sync.aligned.m16n8k16.row.col.f32.bf16.bf16.f32 "
                 "{%0,%1,%2,%3}, {%4,%5,%6,%7}, {%8,%9}, {%0,%1,%2,%3};"
                 : "+f"(d[0]), "+f"(d[1]), "+f"(d[2]), "+f"(d[3])
                 : "r"(a[0]), "r"(a[1]), "r"(a[2]), "r"(a[3]), "r"(b[0]), "r"(b[1]));
}

// split two floats into packed bf16 hi and lo (low element first)
__device__ __forceinline__ void split2(float a, float b, uint32_t& hi, uint32_t& lo) {
    __nv_bfloat16 ha = __float2bfloat16_rn(a), hb = __float2bfloat16_rn(b);
    __nv_bfloat16 la = __float2bfloat16_rn(a - __bfloat162float(ha));
    __nv_bfloat16 lb = __float2bfloat16_rn(b - __bfloat162float(hb));
    __nv_bfloat162 H(ha, hb), L(la, lb);
    hi = *reinterpret_cast<uint32_t*>(&H);
    lo = *reinterpret_cast<uint32_t*>(&L);
}

// ---------------------------------------------------------------------------
// Split fp32 -> (hi, lo) bf16
// ---------------------------------------------------------------------------
__global__ void split_kernel(const float* __restrict__ in,
                             __nv_bfloat16* __restrict__ hi,
                             __nv_bfloat16* __restrict__ lo, int n4) {
    int i = blockIdx.x * blockDim.x + threadIdx.x;
    if (i >= n4) return;
    float4 v = ((const float4*)in)[i];
    float f[4] = {v.x, v.y, v.z, v.w};
    __nv_bfloat16 h[4], l[4];
#pragma unroll
    for (int j = 0; j < 4; j++) {
        h[j] = __float2bfloat16(f[j]);
        l[j] = __float2bfloat16(f[j] - __bfloat162float(h[j]));
    }
    ((__nv_bfloat162*)hi)[2 * i]     = __nv_bfloat162(h[0], h[1]);
    ((__nv_bfloat162*)hi)[2 * i + 1] = __nv_bfloat162(h[2], h[3]);
    ((__nv_bfloat162*)lo)[2 * i]     = __nv_bfloat162(l[0], l[1]);
    ((__nv_bfloat162*)lo)[2 * i + 1] = __nv_bfloat162(l[2], l[3]);
}

// ---------------------------------------------------------------------------
// Tiled-transpose pack of Wq/Wk/Wv (H,C,HS) -> B^T (3072 x 1024) hi/lo.
// ---------------------------------------------------------------------------
__global__ void packw_t_kernel(const float* __restrict__ Wq, const float* __restrict__ Wk,
                               const float* __restrict__ Wv,
                               __nv_bfloat16* __restrict__ bh, __nv_bfloat16* __restrict__ bl) {
    __shared__ float tile[32][33];
    const int wh = blockIdx.z;
    const int w = wh >> 4;
    const int h = wh & 15;
    const float* W = (w == 0) ? Wq : ((w == 1) ? Wk : Wv);
    const int d0 = blockIdx.x * 32;
    const int c0 = blockIdx.y * 32;
    const int tx = threadIdx.x;
    const int ty = threadIdx.y;

#pragma unroll
    for (int i = 0; i < 32; i += 8) {
        int c = c0 + ty + i;
        tile[ty + i][tx] = W[((size_t)h * Cz + c) * HSz + d0 + tx];
    }
    __syncthreads();
#pragma unroll
    for (int i = 0; i < 32; i += 8) {
        int d = d0 + ty + i;
        float v = tile[tx][ty + i];
        __nv_bfloat16 hi = __float2bfloat16(v);
        size_t n = (size_t)w * 1024 + h * 64 + d;
        bh[n * Cz + c0 + tx] = hi;
        bl[n * Cz + c0 + tx] = __float2bfloat16(v - __bfloat162float(hi));
    }
}

// proj_w (K,N) -> proj_w^T (N,K) hi/lo, tiled transpose.
__global__ void packp_t_kernel(const float* __restrict__ pw,
                               __nv_bfloat16* __restrict__ ph, __nv_bfloat16* __restrict__ pl) {
    __shared__ float tile[32][33];
    const int n0 = blockIdx.x * 32;
    const int k0 = blockIdx.y * 32;
    const int tx = threadIdx.x;
    const int ty = threadIdx.y;
#pragma unroll
    for (int i = 0; i < 32; i += 8) {
        int k = k0 + ty + i;
        tile[ty + i][tx] = pw[(size_t)k * Cz + n0 + tx];
    }
    __syncthreads();
#pragma unroll
    for (int i = 0; i < 32; i += 8) {
        int n = n0 + ty + i;
        float v = tile[tx][ty + i];
        __nv_bfloat16 hi = __float2bfloat16(v);
        ph[(size_t)n * Cz + k0 + tx] = hi;
        pl[(size_t)n * Cz + k0 + tx] = __float2bfloat16(v - __bfloat162float(hi));
    }
}

// ---------------------------------------------------------------------------
// mma.sync split-bf16 GEMM, 128x128 CTA tile, K-chunk 64, 2-stage cp.async.
// (proven round-12 structure, 402us)  3-term: Ah*Bh + Al*Bh + Ah*Bl.
// ---------------------------------------------------------------------------
#define GT_BYTES 16384
#define GSTAGE (4 * GT_BYTES)     // 65536 per stage
#define NCHUNK (Kz / 64)          // 16

__global__ __launch_bounds__(256)
void mma_gemm_kernel(const __nv_bfloat16* __restrict__ Ah, const __nv_bfloat16* __restrict__ Al,
                     const __nv_bfloat16* __restrict__ Bh, const __nv_bfloat16* __restrict__ Bl,
                     float* __restrict__ Cf, const float* __restrict__ bias, int N,
                     __nv_bfloat16* __restrict__ Ch, __nv_bfloat16* __restrict__ Cl) {
    extern __shared__ char dyn_smem[];
    const uint32_t sb = smem_u32(dyn_smem);

    const int tid  = threadIdx.x;
    const int wid  = tid >> 5;
    const int lane = tid & 31;
    const int wm = wid >> 2;
    const int wn = wid & 3;
    const size_t bn = (size_t)blockIdx.x * 128;
    const size_t bm = (size_t)blockIdx.y * 128;

    const int lr = lane & 7;
    const uint32_t sw = (uint32_t)lr << 4;
    const uint32_t aRow = (uint32_t)(wm * 64 + lr + ((lane >> 3) & 1) * 8) * 128;
    const uint32_t aCsel = ((lane >> 4) & 1) * 16;
    const uint32_t bRow = (uint32_t)(wn * 32 + lr + ((lane >> 4) & 1) * 8) * 128;
    const uint32_t bCsel = ((lane >> 3) & 1) * 16;

    float acc[4][4][4];
#pragma unroll
    for (int i = 0; i < 4; i++)
#pragma unroll
        for (int j = 0; j < 4; j++)
#pragma unroll
            for (int q = 0; q < 4; q++) acc[i][j][q] = 0.f;

    const __nv_bfloat16* srcs[4] = {Ah + bm * Kz, Al + bm * Kz, Bh + bn * Kz, Bl + bn * Kz};

    size_t goff[4];
    uint32_t soff[4];
#pragma unroll
    for (int i = 0; i < 4; i++) {
        int slot = tid + i * 256;
        int r = slot >> 3;
        int g = slot & 7;
        goff[i] = (size_t)r * Kz + g * 8;
        soff[i] = (uint32_t)(r * 128) + (((uint32_t)g * 16) ^ (((uint32_t)r & 7) * 16));
    }

#define GEMM_ISSUE(kc, stbase)                                                  \
    do {                                                                        \
        _Pragma("unroll")                                                       \
        for (int j = 0; j < 4; j++) {                                           \
            const __nv_bfloat16* s_ = srcs[j] + (kc) * 64;                      \
            _Pragma("unroll")                                                   \
            for (int i = 0; i < 4; i++)                                         \
                cpasync16((stbase) + j * GT_BYTES + soff[i], s_ + goff[i]);     \
        }                                                                       \
        cp_commit();                                                            \
    } while (0)

    GEMM_ISSUE(0, sb);
    GEMM_ISSUE(1, sb + GSTAGE);

    for (int kc = 0; kc < NCHUNK; kc++) {
        if (kc < NCHUNK - 1) cp_wait1(); else cp_wait0();
        __syncthreads();

        const uint32_t st = sb + (uint32_t)(kc & 1) * GSTAGE;
        const uint32_t sAh = st, sAl = st + GT_BYTES, sBh = st + 2 * GT_BYTES, sBl = st + 3 * GT_BYTES;

#pragma unroll
        for (int ks = 0; ks < 4; ks++) {
            const uint32_t acol = sw ^ ((uint32_t)ks * 32 + aCsel);
            const uint32_t bcol = sw ^ ((uint32_t)ks * 32 + bCsel);
            uint32_t ah[4][4], al[4][4], bb[4][2];
#pragma unroll
            for (int mt = 0; mt < 4; mt++)
                ldmx4(ah[mt], sAh + aRow + mt * 2048 + acol);
#pragma unroll
            for (int mt = 0; mt < 4; mt++)
                ldmx4(al[mt], sAl + aRow + mt * 2048 + acol);
#pragma unroll
            for (int np = 0; np < 2; np++) {
                uint32_t q[4];
                ldmx4(q, sBh + bRow + np * 2048 + bcol);
                bb[np * 2][0] = q[0]; bb[np * 2][1] = q[1];
                bb[np * 2 + 1][0] = q[2]; bb[np * 2 + 1][1] = q[3];
            }
#pragma unroll
            for (int mt = 0; mt < 4; mt++)
#pragma unroll
                for (int nt = 0; nt < 4; nt++) {
                    mma16816(acc[mt][nt], ah[mt], bb[nt]);
                    mma16816(acc[mt][nt], al[mt], bb[nt]);
                }
#pragma unroll
            for (int np = 0; np < 2; np++) {
                uint32_t q[4];
                ldmx4(q, sBl + bRow + np * 2048 + bcol);
                bb[np * 2][0] = q[0]; bb[np * 2][1] = q[1];
                bb[np * 2 + 1][0] = q[2]; bb[np * 2 + 1][1] = q[3];
            }
#pragma unroll
            for (int mt = 0; mt < 4; mt++)
#pragma unroll
                for (int nt = 0; nt < 4; nt++)
                    mma16816(acc[mt][nt], ah[mt], bb[nt]);   // Ah*Bl cross term
        }
        __syncthreads();
        if (kc + 2 < NCHUNK) GEMM_ISSUE(kc + 2, st);
    }

    // Epilogue
    if (Cf) {
#pragma unroll
        for (int mt = 0; mt < 4; mt++) {
            size_t r0 = bm + wm * 64 + mt * 16 + (lane >> 2);
#pragma unroll
            for (int nt = 0; nt < 4; nt++) {
                size_t c0 = bn + wn * 32 + nt * 8 + (lane & 3) * 2;
                float b0 = 0.f, b1 = 0.f;
                if (bias) { b0 = bias[c0]; b1 = bias[c0 + 1]; }
                float2 v0 = {acc[mt][nt][0] + b0, acc[mt][nt][1] + b1};
                float2 v1 = {acc[mt][nt][2] + b0, acc[mt][nt][3] + b1};
                *(float2*)(Cf + r0 * (size_t)N + c0)       = v0;
                *(float2*)(Cf + (r0 + 8) * (size_t)N + c0) = v1;
            }
        }
    } else {
#pragma unroll
        for (int mt = 0; mt < 4; mt++) {
            size_t r0 = bm + wm * 64 + mt * 16 + (lane >> 2);
#pragma unroll
            for (int nt = 0; nt < 4; nt++) {
                size_t c0 = bn + wn * 32 + nt * 8 + (lane & 3) * 2;
                uint32_t h0, l0, h1, l1;
                split2(acc[mt][nt][0], acc[mt][nt][1], h0, l0);
                split2(acc[mt][nt][2], acc[mt][nt][3], h1, l1);
                *(uint32_t*)(Ch + r0 * (size_t)N + c0)       = h0;
                *(uint32_t*)(Cl + r0 * (size_t)N + c0)       = l0;
                *(uint32_t*)(Ch + (r0 + 8) * (size_t)N + c0) = h1;
                *(uint32_t*)(Cl + (r0 + 8) * (size_t)N + c0) = l1;
            }
        }
    }
}

// ---------------------------------------------------------------------------
// mma.sync causal flash attention, 2-stage cp.async K/V pipeline.
// CTA: 256 query rows x one (b,h); 8 warps, each warp owns 32 rows (2 m-tiles).
// Q in dedicated smem (64KB); fragments re-loaded per ks (register relief).
// ---------------------------------------------------------------------------
#define FKT 8192                 // one 64x64 bf16 tile
#define FSTAGE (4 * FKT)         // 32768 per stage (Kh,Kl,Vh,Vl)
#define FQOFF (2 * FSTAGE)       // Q region: Qh 32KB + Ql 32KB
#define FSMEM (2 * FSTAGE + 65536)  // 131072

__global__ __launch_bounds__(256)
void flash_mma_kernel(const __nv_bfloat16* __restrict__ qh_, const __nv_bfloat16* __restrict__ ql_,
                      __nv_bfloat16* __restrict__ oh_, __nv_bfloat16* __restrict__ ol_) {
    extern __shared__ char dyn_smem[];
    const uint32_t sb = smem_u32(dyn_smem);
    const uint32_t sQh = sb + FQOFF, sQl = sb + FQOFF + 32768;

    const int tid = threadIdx.x;
    const int wid = tid >> 5;
    const int lane = tid & 31;
    const int lr = lane & 7;
    const uint32_t sw = (uint32_t)lr << 4;
    const int qt = gridDim.x - 1 - blockIdx.x;     // heavy tiles first
    const int t0 = qt * 256;
    const int b  = blockIdx.y >> 4;
    const int h  = blockIdx.y & 15;

    const size_t rowoff = (size_t)(b * Tz) * N3 + h * HSz;
    const __nv_bfloat16* Qsh = qh_ + rowoff;
    const __nv_bfloat16* Qsl = ql_ + rowoff;
    const __nv_bfloat16* kvsrc[4] = {Qsh + Cz, Qsl + Cz, Qsh + 2 * Cz, Qsl + 2 * Cz};

    // ---- Stage Q (256 rows x 64 bf16, hi+lo) into dedicated region ----
    {
        const __nv_bfloat16* qsrc[2] = {Qsh, Qsl};
        const uint32_t qdst[2] = {sQh, sQl};
#pragma unroll
        for (int j = 0; j < 2; j++)
#pragma unroll
            for (int i = 0; i < 8; i++) {
                int slot = tid + i * 256;            // 0..2047
                int r = slot >> 3;                   // 0..255
                int g = slot & 7;
                uint4 v = *(const uint4*)(qsrc[j] + (size_t)(t0 + r) * N3 + g * 8);
                uint32_t off = (uint32_t)(r * 128) + (((uint32_t)g * 16) ^ (((uint32_t)r & 7) * 16));
                asm volatile("st.shared.v4.b32 [%0], {%1,%2,%3,%4};"
                             :: "r"(qdst[j] + off), "r"(v.x), "r"(v.y), "r"(v.z), "r"(v.w));
            }
    }
    __syncthreads();

    float o[2][8][4];
#pragma unroll
    for (int mt = 0; mt < 2; mt++)
#pragma unroll
        for (int i = 0; i < 8; i++)
#pragma unroll
            for (int j = 0; j < 4; j++) o[mt][i][j] = 0.f;
    float m0[2] = {-1e30f, -1e30f}, m1[2] = {-1e30f, -1e30f};
    float l0[2] = {0.f, 0.f}, l1[2] = {0.f, 0.f};

    const int wrow = t0 + wid * 32;                  // warp's first q row
    int gr0[2], gr1[2];
#pragma unroll
    for (int mt = 0; mt < 2; mt++) {
        gr0[mt] = wrow + mt * 16 + (lane >> 2);
        gr1[mt] = gr0[mt] + 8;
    }

    // Q fragment addressing (A operand): row base per m-tile
    uint32_t aoffm[2];
#pragma unroll
    for (int mt = 0; mt < 2; mt++)
        aoffm[mt] = (uint32_t)(wid * 32 + mt * 16 + lr + ((lane >> 3) & 1) * 8) * 128;
    const uint32_t acs = ((lane >> 4) & 1) * 16;

    const uint32_t krow = (uint32_t)(((lane >> 4) & 1) * 8 + lr);
    const uint32_t kcs = ((lane >> 3) & 1) * 16;
    const uint32_t vrow = (uint32_t)(((lane >> 3) & 1) * 8 + lr);
    const uint32_t vcs = ((lane >> 4) & 1) * 16;

    // per-thread K/V load geometry: 2 x 16B per tile
    size_t fgoff[2];
    uint32_t fsoff[2];
#pragma unroll
    for (int i = 0; i < 2; i++) {
        int slot = tid + i * 256;
        int r = slot >> 3;
        int g = slot & 7;
        fgoff[i] = (size_t)r * N3 + g * 8;
        fsoff[i] = (uint32_t)(r * 128) + (((uint32_t)g * 16) ^ (((uint32_t)r & 7) * 16));
    }

#define FLASH_ISSUE(it, stbase)                                                 \
    do {                                                                        \
        const size_t kb_ = (size_t)(it) * 64 * N3;                              \
        _Pragma("unroll")                                                       \
        for (int j = 0; j < 4; j++) {                                           \
            _Pragma("unroll")                                                   \
            for (int i = 0; i < 2; i++)                                         \
                cpasync16((stbase) + j * FKT + fsoff[i], kvsrc[j] + kb_ + fgoff[i]); \
        }                                                                       \
        cp_commit();                                                            \
    } while (0)

    const int nkt = 4 * qt + 4;    // key tiles of 64 covering t0+256 rows
    FLASH_ISSUE(0, sb);
    FLASH_ISSUE(1, sb + FSTAGE);

    for (int it = 0; it < nkt; it++) {
        const int kt0 = it * 64;
        if (it < nkt - 1) cp_wait1(); else cp_wait0();
        __syncthreads();

        const uint32_t st = sb + (uint32_t)(it & 1) * FSTAGE;
        const uint32_t sKh = st, sKl = st + FKT, sVh = st + 2 * FKT, sVl = st + 3 * FKT;

        const bool alive = (kt0 <= wrow + 31);
        if (alive) {
            // ---- S = Q K^T : 32x64 per warp (2 m-tiles), 3-term split ----
            float s[2][8][4];
#pragma unroll
            for (int mt = 0; mt < 2; mt++)
#pragma unroll
                for (int i = 0; i < 8; i++)
#pragma unroll
                    for (int j = 0; j < 4; j++) s[mt][i][j] = 0.f;

#pragma unroll
            for (int ks = 0; ks < 4; ks++) {
                const uint32_t qcol = (((uint32_t)ks * 32 + acs) ^ sw);
                uint32_t qh[2][4], ql[2][4], bb[8][2];
#pragma unroll
                for (int mt = 0; mt < 2; mt++) {
                    ldmx4(qh[mt], sQh + aoffm[mt] + qcol);
                    ldmx4(ql[mt], sQl + aoffm[mt] + qcol);
                }
#pragma unroll
                for (int np = 0; np < 4; np++) {
                    uint32_t q[4];
                    ldmx4(q, sKh + (np * 16 + krow) * 128 + (((uint32_t)ks * 32 + kcs) ^ sw));
                    bb[np * 2][0] = q[0]; bb[np * 2][1] = q[1];
                    bb[np * 2 + 1][0] = q[2]; bb[np * 2 + 1][1] = q[3];
                }
#pragma unroll
                for (int mt = 0; mt < 2; mt++)
#pragma unroll
                    for (int nt = 0; nt < 8; nt++) {
                        mma16816(s[mt][nt], qh[mt], bb[nt]);
                        mma16816(s[mt][nt], ql[mt], bb[nt]);
                    }
#pragma unroll
                for (int np = 0; np < 4; np++) {
                    uint32_t q[4];
                    ldmx4(q, sKl + (np * 16 + krow) * 128 + (((uint32_t)ks * 32 + kcs) ^ sw));
                    bb[np * 2][0] = q[0]; bb[np * 2][1] = q[1];
                    bb[np * 2 + 1][0] = q[2]; bb[np * 2 + 1][1] = q[3];
                }
#pragma unroll
                for (int mt = 0; mt < 2; mt++)
#pragma unroll
                    for (int nt = 0; nt < 8; nt++)
                        mma16816(s[mt][nt], qh[mt], bb[nt]);   // Qh*Kl cross term
            }

            // ---- causal mask (per m-tile) ----
#pragma unroll
            for (int mt = 0; mt < 2; mt++) {
                if (kt0 + 63 > wrow + mt * 16) {
                    const int cbase = kt0 + 2 * (lane & 3);
#pragma unroll
                    for (int nt = 0; nt < 8; nt++) {
                        int col = cbase + nt * 8;
                        if (col     > gr0[mt]) s[mt][nt][0] = -1e30f;
                        if (col + 1 > gr0[mt]) s[mt][nt][1] = -1e30f;
                        if (col     > gr1[mt]) s[mt][nt][2] = -1e30f;
                        if (col + 1 > gr1[mt]) s[mt][nt][3] = -1e30f;
                    }
                }
            }

            // ---- online softmax (warp-local; quad shuffles), per m-tile ----
#pragma unroll
            for (int mt = 0; mt < 2; mt++) {
                float mx0 = m0[mt], mx1 = m1[mt];
#pragma unroll
                for (int nt = 0; nt < 8; nt++) {
                    mx0 = fmaxf(mx0, fmaxf(s[mt][nt][0], s[mt][nt][1]));
                    mx1 = fmaxf(mx1, fmaxf(s[mt][nt][2], s[mt][nt][3]));
                }
                mx0 = fmaxf(mx0, __shfl_xor_sync(0xffffffffu, mx0, 1));
                mx0 = fmaxf(mx0, __shfl_xor_sync(0xffffffffu, mx0, 2));
                mx1 = fmaxf(mx1, __shfl_xor_sync(0xffffffffu, mx1, 1));
                mx1 = fmaxf(mx1, __shfl_xor_sync(0xffffffffu, mx1, 2));
                float corr0 = __expf(m0[mt] - mx0);
                float corr1 = __expf(m1[mt] - mx1);
                float sum0 = 0.f, sum1 = 0.f;
#pragma unroll
                for (int nt = 0; nt < 8; nt++) {
                    s[mt][nt][0] = __expf(s[mt][nt][0] - mx0); sum0 += s[mt][nt][0];
                    s[mt][nt][1] = __expf(s[mt][nt][1] - mx0); sum0 += s[mt][nt][1];
                    s[mt][nt][2] = __expf(s[mt][nt][2] - mx1); sum1 += s[mt][nt][2];
                    s[mt][nt][3] = __expf(s[mt][nt][3] - mx1); sum1 += s[mt][nt][3];
                }
                sum0 += __shfl_xor_sync(0xffffffffu, sum0, 1);
                sum0 += __shfl_xor_sync(0xffffffffu, sum0, 2);
                sum1 += __shfl_xor_sync(0xffffffffu, sum1, 1);
                sum1 += __shfl_xor_sync(0xffffffffu, sum1, 2);
                m0[mt] = mx0; m1[mt] = mx1;
                l0[mt] = l0[mt] * corr0 + sum0;
                l1[mt] = l1[mt] * corr1 + sum1;
#pragma unroll
                for (int nt = 0; nt < 8; nt++) {
                    o[mt][nt][0] *= corr0; o[mt][nt][1] *= corr0;
                    o[mt][nt][2] *= corr1; o[mt][nt][3] *= corr1;
                }
            }

            // ---- O += P V : shared V fragments across both m-tiles ----
#pragma unroll
            for (int ks = 0; ks < 4; ks++) {
                uint32_t pah[2][4], pal[2][4];
#pragma unroll
                for (int mt = 0; mt < 2; mt++) {
                    split2(s[mt][2 * ks][0],     s[mt][2 * ks][1],     pah[mt][0], pal[mt][0]);
                    split2(s[mt][2 * ks][2],     s[mt][2 * ks][3],     pah[mt][1], pal[mt][1]);
                    split2(s[mt][2 * ks + 1][0], s[mt][2 * ks + 1][1], pah[mt][2], pal[mt][2]);
                    split2(s[mt][2 * ks + 1][2], s[mt][2 * ks + 1][3], pah[mt][3], pal[mt][3]);
                }

                uint32_t bv[8][2];
#pragma unroll
                for (int np = 0; np < 4; np++) {
                    uint32_t q[4];
                    ldmx4t(q, sVh + (ks * 16 + vrow) * 128 + (((uint32_t)np * 32 + vcs) ^ sw));
                    bv[np * 2][0] = q[0]; bv[np * 2][1] = q[1];
                    bv[np * 2 + 1][0] = q[2]; bv[np * 2 + 1][1] = q[3];
                }
#pragma unroll
                for (int mt = 0; mt < 2; mt++)
#pragma unroll
                    for (int nt = 0; nt < 8; nt++) {
                        mma16816(o[mt][nt], pah[mt], bv[nt]);
                        mma16816(o[mt][nt], pal[mt], bv[nt]);
                    }
#pragma unroll
                for (int np = 0; np < 4; np++) {
                    uint32_t q[4];
                    ldmx4t(q, sVl + (ks * 16 + vrow) * 128 + (((uint32_t)np * 32 + vcs) ^ sw));
                    bv[np * 2][0] = q[0]; bv[np * 2][1] = q[1];
                    bv[np * 2 + 1][0] = q[2]; bv[np * 2 + 1][1] = q[3];
                }
#pragma unroll
                for (int mt = 0; mt < 2; mt++)
#pragma unroll
                    for (int nt = 0; nt < 8; nt++)
                        mma16816(o[mt][nt], pah[mt], bv[nt]);   // Ph*Vl cross term
            }
        }
        __syncthreads();
        if (it + 2 < nkt) FLASH_ISSUE(it + 2, st);
    }

    // ---- epilogue: normalize, split to bf16 hi/lo, write (B*T, C) ----
    const size_t obase = (size_t)b * Tz;
#pragma unroll
    for (int mt = 0; mt < 2; mt++) {
        const float inv0 = 1.f / l0[mt];
        const float inv1 = 1.f / l1[mt];
#pragma unroll
        for (int nt = 0; nt < 8; nt++) {
            size_t col = (size_t)h * HSz + nt * 8 + 2 * (lane & 3);
            uint32_t h0, lo0, h1, lo1;
            split2(o[mt][nt][0] * inv0, o[mt][nt][1] * inv0, h0, lo0);
            split2(o[mt][nt][2] * inv1, o[mt][nt][3] * inv1, h1, lo1);
            *(uint32_t*)(oh_ + (obase + gr0[mt]) * Cz + col) = h0;
            *(uint32_t*)(ol_ + (obase + gr0[mt]) * Cz + col) = lo0;
            *(uint32_t*)(oh_ + (obase + gr1[mt]) * Cz + col) = h1;
            *(uint32_t*)(ol_ + (obase + gr1[mt]) * Cz + col) = lo1;
        }
    }
}

// ---------------------------------------------------------------------------
// Launch
// ---------------------------------------------------------------------------
extern "C" void kernel_launch(void* const* d_in, const int* in_sizes, int n_in,
                              void* d_out, int out_size) {
    (void)in_sizes; (void)n_in; (void)out_size;
    const float* x  = (const float*)d_in[0];
    const float* Wk = (const float*)d_in[1];
    const float* Wq = (const float*)d_in[2];
    const float* Wv = (const float*)d_in[3];
    const float* pw = (const float*)d_in[4];
    const float* pb = (const float*)d_in[5];
    float* out = (float*)d_out;

    __nv_bfloat16 *xh, *xl, *bTh, *bTl, *pTh, *pTl, *qkvh, *qkvl, *ah, *al;
    cudaGetSymbolAddress((void**)&xh,   g_xh);
    cudaGetSymbolAddress((void**)&xl,   g_xl);
    cudaGetSymbolAddress((void**)&bTh,  g_bTh);
    cudaGetSymbolAddress((void**)&bTl,  g_bTl);
    cudaGetSymbolAddress((void**)&pTh,  g_pTh);
    cudaGetSymbolAddress((void**)&pTl,  g_pTl);
    cudaGetSymbolAddress((void**)&qkvh, g_qkvh);
    cudaGetSymbolAddress((void**)&qkvl, g_qkvl);
    cudaGetSymbolAddress((void**)&ah,   g_ah);
    cudaGetSymbolAddress((void**)&al,   g_al);

    const int gemm_smem = 2 * GSTAGE;      // 131072
    cudaFuncSetAttribute(mma_gemm_kernel, cudaFuncAttributeMaxDynamicSharedMemorySize, gemm_smem);
    cudaFuncSetAttribute(flash_mma_kernel, cudaFuncAttributeMaxDynamicSharedMemorySize, FSMEM);

    // 1. split x, pack+split weights
    split_kernel<<<(Mz * Cz / 4 + 255) / 256, 256>>>(x, xh, xl, Mz * Cz / 4);
    packw_t_kernel<<<dim3(HSz / 32, Cz / 32, 3 * Hz), dim3(32, 8)>>>(Wq, Wk, Wv, bTh, bTl);
    packp_t_kernel<<<dim3(Cz / 32, Cz / 32), dim3(32, 8)>>>(pw, pTh, pTl);

    // 2. QKV projection -> bf16 hi/lo qkv
    mma_gemm_kernel<<<dim3(N3 / 128, Mz / 128), 256, gemm_smem>>>(
        xh, xl, bTh, bTl, nullptr, nullptr, N3, qkvh, qkvl);

    // 3. mma flash attention -> bf16 hi/lo attn (256-row CTAs)
    flash_mma_kernel<<<dim3(Tz / 256, Bz * Hz), 256, FSMEM>>>(qkvh, qkvl, ah, al);

    // 4. output projection + bias -> fp32 out
    mma_gemm_kernel<<<dim3(Cz / 128, Mz / 128), 256, gemm_smem>>>(
        ah, al, pTh, pTl, out, pb, Cz, nullptr, nullptr);
}